// round 11
// baseline (speedup 1.0000x reference)
#include <cuda_runtime.h>
#include <cstdint>

// ---------------- problem constants ----------------
#define NPTS    (64*224*224)      // 3,211,264 points
#define KSEL    512
#define TPB     256
#define PPT     86
#define CTA_PTS (TPB*PPT)         // 22016
#define GRID_F  146               // 146*22016 >= NPTS
#define NW      8                 // warps per CTA
#define ROWPX   9408              // 42 rows * 224
#define NCB     5                 // col blocks of 45 px
#define NZB     64
#define NGV     (3*NCB*NZB)       // 960 valid groups
#define NG_TOT  (NGV+1)           // + junk group

#define FXF  ((float)(11200.0/20.995))        // WIDTH*FOCAL/20.995
#define COSF ((float)0.8386705679454240)      // cos(33 deg)
#define SINF ((float)0.5446390350150271)      // sin(33 deg)

// ---- dynamic smem layout (bytes) ----
#define OFF_WY     0                          // f32, 256 threads * 87-word stride
#define OFF_WZ     89088
#define OFF_LIDX   178176                     // u16[22016]
#define OFF_UG     222208                     // f32[224] (ug == vg table)
#define OFF_START  223104                     // u32[NG_TOT+1]
#define OFF_CUR    226952                     // u32[NG_TOT]
#define SMEM_BYTES 230796

__device__ __forceinline__ float pinff(){ return __int_as_float(0x7f800000); }
__device__ __forceinline__ float ninff(){ return __int_as_float(0xff800000); }

__device__ __forceinline__ unsigned fenc(float f){
    unsigned u = __float_as_uint(f);
    return (u & 0x80000000u) ? ~u : (u | 0x80000000u);
}
__device__ __forceinline__ unsigned ld_acq_u32(const unsigned* p){
    unsigned v;
    asm volatile("ld.acquire.gpu.global.b32 %0, [%1];" : "=r"(v) : "l"(p) : "memory");
    return v;
}
__device__ __forceinline__ uint4 ld_acq_v4(const uint4* p){
    uint4 v;
    asm volatile("ld.acquire.gpu.global.v4.b32 {%0,%1,%2,%3}, [%4];"
                 : "=r"(v.x), "=r"(v.y), "=r"(v.z), "=r"(v.w) : "l"(p) : "memory");
    return v;
}
__device__ __forceinline__ uint4 ld_rlx_v4(const uint4* p){
    uint4 v;
    asm volatile("ld.relaxed.gpu.global.v4.b32 {%0,%1,%2,%3}, [%4];"
                 : "=r"(v.x), "=r"(v.y), "=r"(v.z), "=r"(v.w) : "l"(p) : "memory");
    return v;
}
__device__ __forceinline__ void st_rlx_v4(uint4* p, uint4 v){
    asm volatile("st.relaxed.gpu.global.v4.b32 [%0], {%1,%2,%3,%4};"
                 :: "l"(p), "r"(v.x), "r"(v.y), "r"(v.z), "r"(v.w) : "memory");
}
__device__ __forceinline__ void st_rel_v4(uint4* p, uint4 v){
    asm volatile("st.release.gpu.global.v4.b32 [%0], {%1,%2,%3,%4};"
                 :: "l"(p), "r"(v.x), "r"(v.y), "r"(v.z), "r"(v.w) : "memory");
}
__device__ __forceinline__ unsigned long long warp_max_u64(unsigned long long v){
    #pragma unroll
    for (int o = 16; o; o >>= 1){
        unsigned long long w = __shfl_down_sync(0xffffffffu, v, o);
        if (w > v) v = w;
    }
    return v;
}

// ---------------- device scratch (zero-initialized at load) ----------------
__device__ uint4         g_partA[2][GRID_F];   // {tag, keyhi, keylo, wx}
__device__ uint4         g_partB[2][GRID_F];   // {tag, wy, wz, 0}
__device__ int           g_first[GRID_F];
__device__ unsigned int  g_ready;              // monotonic ticket counter
__device__ int           g_sel[KSEL];
__device__ float         g_feat[KSEL*6];
__device__ float         g_h1[KSEL*64];
__device__ float         g_h2[KSEL*128];
__device__ float         g_h3[KSEL*256];
__device__ float         g_h4[KSEL*512];

// world-space point, reference fp32 association (no fma contraction)
__device__ __forceinline__ void worldpt(const float* __restrict__ x, int idx,
                                        float& wx, float& wy, float& wz, bool& valid){
    float Z   = __ldg(&x[idx*5+3]);
    float seg = __ldg(&x[idx*5+4]);
    int col =  idx % 224;
    int row = (idx / 224) % 224;
    float ug = __fdiv_rn((float)(112 - col), FXF);
    float vg = __fdiv_rn((float)(112 - row), FXF);
    float X = __fmul_rn(ug, Z);
    float Y = __fmul_rn(vg, Z);
    wx = X;
    wy = __fadd_rn(__fsub_rn(__fmul_rn(Y, COSF), __fmul_rn(Z, SINF)),  1.5f);
    wz = __fadd_rn(__fadd_rn(__fmul_rn(Y, SINF), __fmul_rn(Z, COSF)), -2.5f);
    valid = (Z < 3.0f) && (seg != 15.0f);
}

__global__ void noop_kernel(){}

// ---------------- persistent FPS kernel ----------------
__global__ void __launch_bounds__(TPB,1) fps_kernel(const float* __restrict__ x){
    extern __shared__ unsigned char smraw[];
    float*    s_wy    = (float*)(smraw + OFF_WY);
    float*    s_wz    = (float*)(smraw + OFF_WZ);
    unsigned short* s_lidx = (unsigned short*)(smraw + OFF_LIDX);
    float*    s_ug    = (float*)(smraw + OFF_UG);   // ug == vg (same table)
    unsigned* s_start = (unsigned*)(smraw + OFF_START);
    unsigned* s_cur   = (unsigned*)(smraw + OFF_CUR);

    __shared__ float s_bc[3];
    __shared__ int   s_fv;
    __shared__ unsigned s_epoch;
    __shared__ unsigned long long s_red[NW];
    __shared__ unsigned long long s_red2[NW];

    const int t    = threadIdx.x;
    const int cta  = blockIdx.x;
    const int base = cta * CTA_PTS;
    const int wid  = t >> 5, lane = t & 31;
    const int so87 = t * 87;          // padded word stride: conflict-free
    const int so86 = t * 86;

    if (t == 0) s_fv = 0x7fffffff;
    for (int i = t; i < 224; i += TPB)
        s_ug[i] = __fdiv_rn((float)(112 - i), FXF);
    for (int g = t; g < NG_TOT; g += TPB) s_cur[g] = 0u;
    __syncthreads();

    // ---- pass 1: histogram ----
    int firstvalid = 0x7fffffff;
    for (int k = 0; k < PPT; ++k){
        int lidx = k*TPB + t;
        int fl   = base + lidx;
        int gid  = NGV;
        if (fl < NPTS){
            float Z   = __ldg(&x[fl*5+3]);
            float seg = __ldg(&x[fl*5+4]);
            bool valid = (Z < 3.0f) && (seg != 15.0f);
            if (valid){
                if (fl < firstvalid) firstvalid = fl;
                int zb  = min(NZB-1, (int)(Z * (float)NZB));
                int col = fl % 224;
                gid = ((lidx / ROWPX) * NCB + col / 45) * NZB + zb;
            }
        }
        atomicAdd(&s_cur[gid], 1u);
    }
    atomicMin(&s_fv, firstvalid);
    __syncthreads();

    // ---- pass 2: serial prefix ----
    if (t == 0){
        unsigned acc = 0;
        for (int g = 0; g < NG_TOT; ++g){
            unsigned c = s_cur[g];
            s_start[g] = acc; s_cur[g] = acc; acc += c;
        }
        s_start[NG_TOT] = acc;
    }
    __syncthreads();

    // ---- pass 3: scatter (exact wy/wz) ----
    for (int k = 0; k < PPT; ++k){
        int lidx = k*TPB + t;
        int fl   = base + lidx;
        int gid  = NGV;
        float wy = 0.f, wz = 0.f;
        if (fl < NPTS){
            float Z   = __ldg(&x[fl*5+3]);
            float seg = __ldg(&x[fl*5+4]);
            bool valid = (Z < 3.0f) && (seg != 15.0f);
            if (valid){
                int zb  = min(NZB-1, (int)(Z * (float)NZB));
                int col = fl % 224;
                int row = (fl / 224) % 224;
                gid = ((lidx / ROWPX) * NCB + col / 45) * NZB + zb;
                float Y = __fmul_rn(s_ug[row], Z);
                wy = __fadd_rn(__fsub_rn(__fmul_rn(Y, COSF), __fmul_rn(Z, SINF)),  1.5f);
                wz = __fadd_rn(__fadd_rn(__fmul_rn(Y, SINF), __fmul_rn(Z, COSF)), -2.5f);
            }
        }
        unsigned pos = atomicAdd(&s_cur[gid], 1u);
        int tw = (int)(pos / PPT) * 87 + (int)(pos % PPT);
        s_wy[tw] = wy;
        s_wz[tw] = wz;
        s_lidx[pos] = (unsigned short)lidx;
    }
    __syncthreads();

    // ---- owner init: thread owns sorted slots [t*86, t*86+86) ----
    float mind[PPT];
    float wxr [PPT];
    float ax = 0.f, ay = 0.f, az = 0.f, rad = 0.f;
    float gmax;
    unsigned long long gkey;
    float pwx = 0.f, pwy = 0.f, pwz = 0.f;    // coords of this thread's current best
    {
        const unsigned junkstart = s_start[NGV];
        bool anyv = false; float maxd2 = 0.f;
        #pragma unroll 4
        for (int k = 0; k < PPT; ++k){
            unsigned pos = (unsigned)(so86 + k);
            bool valid = pos < junkstart;
            float wx = 0.f;
            if (valid){
                int fl = base + (int)s_lidx[pos];
                float Z = __ldg(&x[fl*5+3]);
                wx = __fmul_rn(s_ug[fl % 224], Z);
            }
            wxr[k]  = wx;
            mind[k] = valid ? pinff() : ninff();
            if (valid){
                float wy = s_wy[so87+k], wz = s_wz[so87+k];
                if (!anyv){ ax = wx; ay = wy; az = wz; anyv = true; }
                float dx = wx-ax, dy = wy-ay, dz = wz-az;
                maxd2 = fmaxf(maxd2, dx*dx + dy*dy + dz*dz);
            }
        }
        rad  = sqrtf(maxd2) * (1.0f + 1e-5f) + 1e-7f;
        gmax = anyv ? pinff() : ninff();
        gkey = ((unsigned long long)fenc(gmax) << 32);
    }
    __syncthreads();

    // ---- epoch-ticketed grid barrier (replay-idempotent) ----
    if (t == 0){
        g_first[cta] = s_fv;
        __threadfence();
        unsigned ticket = atomicAdd(&g_ready, 1u);
        unsigned epoch  = ticket / GRID_F;
        unsigned target = (epoch + 1u) * GRID_F;
        while (ld_acq_u32(&g_ready) < target) { }
        s_epoch = epoch;
    }
    __syncthreads();
    const unsigned tagbase = s_epoch * (unsigned)KSEL + 1u;

    // ---- deterministic start ----
    {
        unsigned fv = 0x7fffffffu;
        if (t < GRID_F) fv = ld_acq_u32((const unsigned*)&g_first[t]);
        fv = __reduce_min_sync(0xffffffffu, fv);
        if (lane == 0) s_red[wid] = fv;
        __syncthreads();
        if (t == 0){
            unsigned s = (unsigned)s_red[0];
            for (int w = 1; w < NW; ++w) s = min(s, (unsigned)s_red[w]);
            int sp = (s == 0x7fffffffu) ? 0 : (int)s;
            float wx, wy, wz; bool v;
            worldpt(x, sp, wx, wy, wz, v);
            s_bc[0] = wx; s_bc[1] = wy; s_bc[2] = wz;
            if (cta == 0) g_sel[0] = sp;
        }
        __syncthreads();
    }

    // ---- 511 rounds ----
    for (int it = 0; it < KSEL-1; ++it){
        const float cx = s_bc[0], cy = s_bc[1], cz = s_bc[2];
        const unsigned tag = tagbase + (unsigned)it;
        const int p = it & 1;

        // exact chunk prune test
        {
            float dx = cx-ax, dy = cy-ay, dz = cz-az;
            float dc = sqrtf(dx*dx + dy*dy + dz*dz);
            float lb = dc * (1.0f - 1e-5f) - rad;
            bool prune = (lb > 0.f) && (lb*lb*(1.0f - 1e-5f) > gmax*(1.0f + 1e-5f));
            if (!prune){
                // pass 1: distance update + running max (short FMNMX chain)
                float bestv = ninff();
                #pragma unroll
                for (int k = 0; k < PPT; ++k){
                    float dxx = __fsub_rn(wxr[k],       cx);
                    float dyy = __fsub_rn(s_wy[so87+k], cy);
                    float dzz = __fsub_rn(s_wz[so87+k], cz);
                    float d   = __fadd_rn(__fadd_rn(__fmul_rn(dxx,dxx), __fmul_rn(dyy,dyy)),
                                          __fmul_rn(dzz,dzz));
                    float m = fminf(mind[k], d);
                    mind[k] = m;
                    bestv   = fmaxf(bestv, m);
                }
                // pass 2: argmax + STATIC capture of winner coords (no dynamic reg index!)
                unsigned bl = 0xffffffffu;
                float bwx = 0.f, bwy = 0.f, bwz = 0.f;
                #pragma unroll
                for (int k = 0; k < PPT; ++k){
                    if (mind[k] == bestv){
                        unsigned li = s_lidx[so86+k];
                        if (li < bl){
                            bl  = li;
                            bwx = wxr[k];
                            bwy = s_wy[so87+k];
                            bwz = s_wz[so87+k];
                        }
                    }
                }
                gmax = bestv;
                pwx = bwx; pwy = bwy; pwz = bwz;
                gkey = ((unsigned long long)fenc(bestv) << 32)
                     | (unsigned)(~((unsigned)base + bl));
            }
        }

        // block reduce over 256 thread keys
        unsigned long long k1 = warp_max_u64(gkey);
        if (lane == 0) s_red[wid] = k1;
        __syncthreads();
        unsigned long long bk = s_red[0];
        #pragma unroll
        for (int w = 1; w < NW; ++w) if (s_red[w] > bk) bk = s_red[w];

        // winner thread posts key + coords (release orders partB before partA)
        if (gkey == bk){
            uint4 hb = make_uint4(tag, __float_as_uint(pwy), __float_as_uint(pwz), 0u);
            uint4 ha = make_uint4(tag, (unsigned)(bk >> 32), (unsigned)bk,
                                       __float_as_uint(pwx));
            st_rlx_v4(&g_partB[p][cta], hb);
            st_rel_v4(&g_partA[p][cta], ha);
        }

        // gather all CTA partials
        unsigned long long gk = 0ull; float gwx = 0.f, gwy = 0.f, gwz = 0.f;
        if (t < GRID_F){
            uint4 a;
            do { a = ld_acq_v4(&g_partA[p][t]); } while (a.x < tag);
            uint4 b = ld_rlx_v4(&g_partB[p][t]);
            gk  = ((unsigned long long)a.y << 32) | a.z;
            gwx = __uint_as_float(a.w);
            gwy = __uint_as_float(b.y);
            gwz = __uint_as_float(b.z);
        }
        unsigned long long k2 = warp_max_u64(gk);
        if (lane == 0) s_red2[wid] = k2;
        __syncthreads();
        unsigned long long bk2 = s_red2[0];
        #pragma unroll
        for (int w = 1; w < NW; ++w) if (s_red2[w] > bk2) bk2 = s_red2[w];

        if (t < GRID_F && gk == bk2){           // keys unique -> exactly one thread
            s_bc[0] = gwx; s_bc[1] = gwy; s_bc[2] = gwz;
            if (cta == 0) g_sel[it+1] = (int)(~(unsigned)(bk2 & 0xffffffffull));
        }
        __syncthreads();
    }
}

// ---------------- gather selected features ----------------
__global__ void gather_kernel(const float* __restrict__ x, float* __restrict__ feat){
    int t = threadIdx.x;                 // 512 threads
    int idx = g_sel[t];
    float wx, wy, wz; bool v;
    worldpt(x, idx, wx, wy, wz, v);
    feat[t*6+0] = wx;
    feat[t*6+1] = wy;
    feat[t*6+2] = wz;
    feat[t*6+3] = __fdiv_rn(x[idx*5+0], 255.0f);
    feat[t*6+4] = __fdiv_rn(x[idx*5+1], 255.0f);
    feat[t*6+5] = __fdiv_rn(x[idx*5+2], 255.0f);
}

// ---------------- MLP ----------------
template<int D>
__device__ __forceinline__ float block_sum(float v, float* s_red){
    __syncthreads();
    int lane = threadIdx.x & 31, w = threadIdx.x >> 5;
    #pragma unroll
    for (int o = 16; o; o >>= 1) v += __shfl_xor_sync(0xffffffffu, v, o);
    if (lane == 0) s_red[w] = v;
    __syncthreads();
    float s = (threadIdx.x < (D+31)/32) ? s_red[threadIdx.x] : 0.f;
    #pragma unroll
    for (int o = 16; o; o >>= 1) s += __shfl_xor_sync(0xffffffffu, s, o);
    if (threadIdx.x == 0) s_red[0] = s;
    __syncthreads();
    return s_red[0];
}

template<int DIN, int DOUT, bool LNRELU>
__global__ void __launch_bounds__(DOUT) layer_kernel(
    const float* __restrict__ in, const float* __restrict__ W,
    const float* __restrict__ b,  const float* __restrict__ g,
    const float* __restrict__ be, float* __restrict__ out)
{
    __shared__ float s_in[DIN];
    __shared__ float s_red[32];
    const int p = blockIdx.x, t = threadIdx.x;
    for (int k = t; k < DIN; k += DOUT) s_in[k] = in[p*DIN + k];
    __syncthreads();
    float a = b[t];
    #pragma unroll 8
    for (int k = 0; k < DIN; ++k) a = fmaf(s_in[k], W[k*DOUT + t], a);
    if (LNRELU){
        float mean = block_sum<DOUT>(a, s_red) / (float)DOUT;
        float q = a - mean;
        float var = block_sum<DOUT>(q*q, s_red) / (float)DOUT;
        float v = q * rsqrtf(var + 1e-5f) * g[t] + be[t];
        out[p*DOUT + t] = fmaxf(v, 0.f);
    } else {
        out[p*DOUT + t] = a;
    }
}

__global__ void __launch_bounds__(512) final_kernel(
    const float* __restrict__ h4, const float* __restrict__ Wf,
    const float* __restrict__ bf, const float* __restrict__ gf,
    const float* __restrict__ bef, float* __restrict__ out)
{
    __shared__ float pooled[512];
    __shared__ float o[64];
    __shared__ float s_red[4];
    const int t = threadIdx.x;
    float m = ninff();
    for (int p = 0; p < KSEL; ++p) m = fmaxf(m, h4[p*512 + t]);
    pooled[t] = m;
    __syncthreads();
    if (t < 64){
        float a = bf[t];
        #pragma unroll 8
        for (int d = 0; d < 512; ++d) a = fmaf(pooled[d], Wf[d*64 + t], a);
        o[t] = a;
    }
    __syncthreads();
    if (t < 64){
        float s = o[t];
        #pragma unroll
        for (int off = 16; off; off >>= 1) s += __shfl_xor_sync(0xffffffffu, s, off);
        if ((t & 31) == 0) s_red[t >> 5] = s;
    }
    __syncthreads();
    float mean = (s_red[0] + s_red[1]) / 64.f;
    if (t < 64){
        float q = o[t] - mean;
        float s2 = q*q;
        #pragma unroll
        for (int off = 16; off; off >>= 1) s2 += __shfl_xor_sync(0xffffffffu, s2, off);
        if ((t & 31) == 0) s_red[2 + (t >> 5)] = s2;
    }
    __syncthreads();
    if (t < 64){
        float var = (s_red[2] + s_red[3]) / 64.f;
        out[t] = (o[t] - mean) * rsqrtf(var + 1e-5f) * gf[t] + bef[t];
    }
}

// ---------------- launch ----------------
extern "C" void kernel_launch(void* const* d_in, const int* in_sizes, int n_in,
                              void* d_out, int out_size) {
    const float* x = (const float*)d_in[0];
    const float *W1,*b1,*g1,*be1,*W2,*b2,*g2,*be2,*W3,*b3,*g3,*be3,*W4,*b4,*Wf,*bf,*gf,*bef;
    if (n_in > 3 && in_sizes[3] == 64) {
        W1=(const float*)d_in[1];  b1=(const float*)d_in[2];  g1=(const float*)d_in[3];  be1=(const float*)d_in[4];
        W2=(const float*)d_in[5];  b2=(const float*)d_in[6];  g2=(const float*)d_in[7];  be2=(const float*)d_in[8];
        W3=(const float*)d_in[9];  b3=(const float*)d_in[10]; g3=(const float*)d_in[11]; be3=(const float*)d_in[12];
        W4=(const float*)d_in[13]; b4=(const float*)d_in[14];
        Wf=(const float*)d_in[15]; bf=(const float*)d_in[16]; gf=(const float*)d_in[17]; bef=(const float*)d_in[18];
    } else {
        W1=(const float*)d_in[1];  b1=(const float*)d_in[2];
        W2=(const float*)d_in[3];  b2=(const float*)d_in[4];
        W3=(const float*)d_in[5];  b3=(const float*)d_in[6];
        W4=(const float*)d_in[7];  b4=(const float*)d_in[8];
        g1=(const float*)d_in[9];  be1=(const float*)d_in[10];
        g2=(const float*)d_in[11]; be2=(const float*)d_in[12];
        g3=(const float*)d_in[13]; be3=(const float*)d_in[14];
        Wf=(const float*)d_in[15]; bf=(const float*)d_in[16]; gf=(const float*)d_in[17]; bef=(const float*)d_in[18];
    }

    static int attr_done = 0;
    if (!attr_done){
        (void)cudaFuncSetAttribute(fps_kernel, cudaFuncAttributeMaxDynamicSharedMemorySize, SMEM_BYTES);
        attr_done = 1;
    }

    float *feat,*h1,*h2,*h3,*h4;
    cudaGetSymbolAddress((void**)&feat, g_feat);
    cudaGetSymbolAddress((void**)&h1,   g_h1);
    cudaGetSymbolAddress((void**)&h2,   g_h2);
    cudaGetSymbolAddress((void**)&h3,   g_h3);
    cudaGetSymbolAddress((void**)&h4,   g_h4);

    noop_kernel<<<1, 1>>>();
    noop_kernel<<<1, 1>>>();
    noop_kernel<<<1, 1>>>();
    fps_kernel<<<GRID_F, TPB, SMEM_BYTES>>>(x);     // 4th launch (ncu capture slot)
    gather_kernel<<<1, 512>>>(x, feat);
    layer_kernel<  6,  64, true ><<<KSEL,  64>>>(feat, W1, b1, g1, be1, h1);
    layer_kernel< 64, 128, true ><<<KSEL, 128>>>(h1,   W2, b2, g2, be2, h2);
    layer_kernel<128, 256, true ><<<KSEL, 256>>>(h2,   W3, b3, g3, be3, h3);
    layer_kernel<256, 512, false><<<KSEL, 512>>>(h3,   W4, b4, nullptr, nullptr, h4);
    final_kernel<<<1, 512>>>(h4, Wf, bf, gf, bef, (float*)d_out);
}

// round 13
// speedup vs baseline: 1.5532x; 1.5532x over previous
#include <cuda_runtime.h>
#include <cstdint>

// ---------------- problem constants ----------------
#define NPTS    (64*224*224)      // 3,211,264 points
#define KSEL    512
#define TPB     384
#define PPT     57
#define CTA_PTS (TPB*PPT)         // 21888
#define GRID_F  147               // 147*21888 = 3,217,536 >= NPTS
#define NW      12                // warps per CTA
#define ROWPX   7168              // 32 rows * 224 px
#define NCB     7                 // col blocks of 32 px
#define NZB     32
#define NGV     (4*NCB*NZB)       // 896 valid groups
#define NG_TOT  (NGV+1)           // + junk group

#define FXF  ((float)(11200.0/20.995))        // WIDTH*FOCAL/20.995
#define COSF ((float)0.8386705679454240)      // cos(33 deg)
#define SINF ((float)0.5446390350150271)      // sin(33 deg)

// ---- dynamic smem layout (bytes) ----
#define OFF_WY     0                          // f32[384*57] stride 57 (odd: conflict-free)
#define OFF_WZ     87552
#define OFF_LIDX   175104                     // u16[21888]
#define OFF_UG     218880                     // f32[224] (ug == vg table)
#define OFF_START  219776                     // u32[NG_TOT+1]
#define OFF_CUR    223368                     // u32[NG_TOT]
#define SMEM_BYTES 226956

__device__ __forceinline__ float pinff(){ return __int_as_float(0x7f800000); }
__device__ __forceinline__ float ninff(){ return __int_as_float(0xff800000); }

__device__ __forceinline__ unsigned fenc(float f){
    unsigned u = __float_as_uint(f);
    return (u & 0x80000000u) ? ~u : (u | 0x80000000u);
}
__device__ __forceinline__ unsigned ld_acq_u32(const unsigned* p){
    unsigned v;
    asm volatile("ld.acquire.gpu.global.b32 %0, [%1];" : "=r"(v) : "l"(p) : "memory");
    return v;
}
__device__ __forceinline__ uint4 ld_acq_v4(const uint4* p){
    uint4 v;
    asm volatile("ld.acquire.gpu.global.v4.b32 {%0,%1,%2,%3}, [%4];"
                 : "=r"(v.x), "=r"(v.y), "=r"(v.z), "=r"(v.w) : "l"(p) : "memory");
    return v;
}
__device__ __forceinline__ uint4 ld_rlx_v4(const uint4* p){
    uint4 v;
    asm volatile("ld.relaxed.gpu.global.v4.b32 {%0,%1,%2,%3}, [%4];"
                 : "=r"(v.x), "=r"(v.y), "=r"(v.z), "=r"(v.w) : "l"(p) : "memory");
    return v;
}
__device__ __forceinline__ void st_rlx_v4(uint4* p, uint4 v){
    asm volatile("st.relaxed.gpu.global.v4.b32 [%0], {%1,%2,%3,%4};"
                 :: "l"(p), "r"(v.x), "r"(v.y), "r"(v.z), "r"(v.w) : "memory");
}
__device__ __forceinline__ void st_rel_v4(uint4* p, uint4 v){
    asm volatile("st.release.gpu.global.v4.b32 [%0], {%1,%2,%3,%4};"
                 :: "l"(p), "r"(v.x), "r"(v.y), "r"(v.z), "r"(v.w) : "memory");
}
__device__ __forceinline__ unsigned long long warp_max_u64(unsigned long long v){
    #pragma unroll
    for (int o = 16; o; o >>= 1){
        unsigned long long w = __shfl_down_sync(0xffffffffu, v, o);
        if (w > v) v = w;
    }
    return v;
}

// ---------------- device scratch (zero-initialized at load) ----------------
__device__ uint4         g_partA[2][GRID_F];   // {tag, keyhi, keylo, wx}
__device__ uint4         g_partB[2][GRID_F];   // {tag, wy, wz, 0}
__device__ int           g_first[GRID_F];
__device__ unsigned int  g_ready;              // monotonic ticket counter
__device__ int           g_sel[KSEL];
__device__ float         g_feat[KSEL*6];
__device__ float         g_h1[KSEL*64];
__device__ float         g_h2[KSEL*128];
__device__ float         g_h3[KSEL*256];
__device__ float         g_h4[KSEL*512];

// world-space point, reference fp32 association (no fma contraction)
__device__ __forceinline__ void worldpt(const float* __restrict__ x, int idx,
                                        float& wx, float& wy, float& wz, bool& valid){
    float Z   = __ldg(&x[idx*5+3]);
    float seg = __ldg(&x[idx*5+4]);
    int col =  idx % 224;
    int row = (idx / 224) % 224;
    float ug = __fdiv_rn((float)(112 - col), FXF);
    float vg = __fdiv_rn((float)(112 - row), FXF);
    float X = __fmul_rn(ug, Z);
    float Y = __fmul_rn(vg, Z);
    wx = X;
    wy = __fadd_rn(__fsub_rn(__fmul_rn(Y, COSF), __fmul_rn(Z, SINF)),  1.5f);
    wz = __fadd_rn(__fadd_rn(__fmul_rn(Y, SINF), __fmul_rn(Z, COSF)), -2.5f);
    valid = (Z < 3.0f) && (seg != 15.0f);
}

__global__ void noop_kernel(){}

// ---------------- persistent FPS kernel ----------------
__global__ void __launch_bounds__(TPB,1) fps_kernel(const float* __restrict__ x){
    extern __shared__ unsigned char smraw[];
    float*    s_wy    = (float*)(smraw + OFF_WY);
    float*    s_wz    = (float*)(smraw + OFF_WZ);
    unsigned short* s_lidx = (unsigned short*)(smraw + OFF_LIDX);
    float*    s_ug    = (float*)(smraw + OFF_UG);   // ug == vg (same table)
    unsigned* s_start = (unsigned*)(smraw + OFF_START);
    unsigned* s_cur   = (unsigned*)(smraw + OFF_CUR);

    __shared__ float s_bc[3];
    __shared__ int   s_fv;
    __shared__ unsigned s_epoch;
    __shared__ unsigned long long s_red[NW];
    __shared__ unsigned long long s_red2[NW];

    const int t    = threadIdx.x;
    const int cta  = blockIdx.x;
    const int base = cta * CTA_PTS;
    const int wid  = t >> 5, lane = t & 31;
    const int so   = t * PPT;          // owned slot range [so, so+57)

    if (t == 0) s_fv = 0x7fffffff;
    for (int i = t; i < 224; i += TPB)
        s_ug[i] = __fdiv_rn((float)(112 - i), FXF);
    for (int g = t; g < NG_TOT; g += TPB) s_cur[g] = 0u;
    __syncthreads();

    // ---- pass 1: histogram ----
    int firstvalid = 0x7fffffff;
    for (int k = 0; k < PPT; ++k){
        int lidx = k*TPB + t;
        int fl   = base + lidx;
        int gid  = NGV;
        if (fl < NPTS){
            float Z   = __ldg(&x[fl*5+3]);
            float seg = __ldg(&x[fl*5+4]);
            bool valid = (Z < 3.0f) && (seg != 15.0f);
            if (valid){
                if (fl < firstvalid) firstvalid = fl;
                int zb  = min(NZB-1, (int)(Z * (float)NZB));
                int col = fl % 224;
                gid = ((lidx / ROWPX) * NCB + (col >> 5)) * NZB + zb;
            }
        }
        atomicAdd(&s_cur[gid], 1u);
    }
    atomicMin(&s_fv, firstvalid);
    __syncthreads();

    // ---- pass 2: serial prefix ----
    if (t == 0){
        unsigned acc = 0;
        for (int g = 0; g < NG_TOT; ++g){
            unsigned c = s_cur[g];
            s_start[g] = acc; s_cur[g] = acc; acc += c;
        }
        s_start[NG_TOT] = acc;
    }
    __syncthreads();

    // ---- pass 3: scatter (exact wy/wz) ----
    for (int k = 0; k < PPT; ++k){
        int lidx = k*TPB + t;
        int fl   = base + lidx;
        int gid  = NGV;
        float wy = 0.f, wz = 0.f;
        if (fl < NPTS){
            float Z   = __ldg(&x[fl*5+3]);
            float seg = __ldg(&x[fl*5+4]);
            bool valid = (Z < 3.0f) && (seg != 15.0f);
            if (valid){
                int zb  = min(NZB-1, (int)(Z * (float)NZB));
                int col = fl % 224;
                int row = (fl / 224) % 224;
                gid = ((lidx / ROWPX) * NCB + (col >> 5)) * NZB + zb;
                float Y = __fmul_rn(s_ug[row], Z);
                wy = __fadd_rn(__fsub_rn(__fmul_rn(Y, COSF), __fmul_rn(Z, SINF)),  1.5f);
                wz = __fadd_rn(__fadd_rn(__fmul_rn(Y, SINF), __fmul_rn(Z, COSF)), -2.5f);
            }
        }
        unsigned pos = atomicAdd(&s_cur[gid], 1u);
        s_wy[pos] = wy;
        s_wz[pos] = wz;
        s_lidx[pos] = (unsigned short)lidx;
    }
    __syncthreads();

    // ---- owner init: thread owns sorted slots [so, so+57) ----
    float mind[PPT];
    float wxr [PPT];
    float ax = 0.f, ay = 0.f, az = 0.f, rad = 0.f;
    float gmax;
    unsigned long long gkey;
    float pwx = 0.f; int pslot = 0;           // winner coord cache (wx + slot)
    {
        const unsigned junkstart = s_start[NGV];
        bool anyv = false; float maxd2 = 0.f;
        #pragma unroll 4
        for (int k = 0; k < PPT; ++k){
            unsigned pos = (unsigned)(so + k);
            bool valid = pos < junkstart;
            float wx = 0.f;
            if (valid){
                int fl = base + (int)s_lidx[pos];
                float Z = __ldg(&x[fl*5+3]);
                wx = __fmul_rn(s_ug[fl % 224], Z);
            }
            wxr[k]  = wx;
            mind[k] = valid ? pinff() : ninff();
            if (valid){
                float wy = s_wy[pos], wz = s_wz[pos];
                if (!anyv){ ax = wx; ay = wy; az = wz; anyv = true; }
                float dx = wx-ax, dy = wy-ay, dz = wz-az;
                maxd2 = fmaxf(maxd2, dx*dx + dy*dy + dz*dz);
            }
        }
        rad  = sqrtf(maxd2) * (1.0f + 1e-5f) + 1e-7f;
        gmax = anyv ? pinff() : ninff();
        gkey = ((unsigned long long)fenc(gmax) << 32);
    }
    __syncthreads();

    // ---- epoch-ticketed grid barrier (replay-idempotent) ----
    if (t == 0){
        g_first[cta] = s_fv;
        __threadfence();
        unsigned ticket = atomicAdd(&g_ready, 1u);
        unsigned epoch  = ticket / GRID_F;
        unsigned target = (epoch + 1u) * GRID_F;
        while (ld_acq_u32(&g_ready) < target) { }
        s_epoch = epoch;
    }
    __syncthreads();
    const unsigned tagbase = s_epoch * (unsigned)KSEL + 1u;

    // ---- deterministic start ----
    {
        unsigned fv = 0x7fffffffu;
        if (t < GRID_F) fv = ld_acq_u32((const unsigned*)&g_first[t]);
        fv = __reduce_min_sync(0xffffffffu, fv);
        if (lane == 0) s_red[wid] = fv;
        __syncthreads();
        if (t == 0){
            unsigned s = (unsigned)s_red[0];
            for (int w = 1; w < NW; ++w) s = min(s, (unsigned)s_red[w]);
            int sp = (s == 0x7fffffffu) ? 0 : (int)s;
            float wx, wy, wz; bool v;
            worldpt(x, sp, wx, wy, wz, v);
            s_bc[0] = wx; s_bc[1] = wy; s_bc[2] = wz;
            if (cta == 0) g_sel[0] = sp;
        }
        __syncthreads();
    }

    // ---- 511 rounds ----
    for (int it = 0; it < KSEL-1; ++it){
        const float cx = s_bc[0], cy = s_bc[1], cz = s_bc[2];
        const unsigned tag = tagbase + (unsigned)it;
        const int p = it & 1;

        // exact chunk prune test (conservative margins; skipped updates provably no-ops)
        {
            float dx = cx-ax, dy = cy-ay, dz = cz-az;
            float dc = sqrtf(dx*dx + dy*dy + dz*dz);
            float lb = dc * (1.0f - 1e-5f) - rad;
            bool prune = (lb > 0.f) && (lb*lb*(1.0f - 1e-5f) > gmax*(1.0f + 1e-5f));
            if (!prune){
                // pass 1: distance update + running max (short FMNMX chain)
                float bestv = ninff();
                #pragma unroll
                for (int k = 0; k < PPT; ++k){
                    float dxx = __fsub_rn(wxr[k],     cx);
                    float dyy = __fsub_rn(s_wy[so+k], cy);
                    float dzz = __fsub_rn(s_wz[so+k], cz);
                    float d   = __fadd_rn(__fadd_rn(__fmul_rn(dxx,dxx), __fmul_rn(dyy,dyy)),
                                          __fmul_rn(dzz,dzz));
                    float m = fminf(mind[k], d);
                    mind[k] = m;
                    bestv   = fmaxf(bestv, m);
                }
                // pass 2: argmax (lowest lidx) + static capture of wx and slot
                unsigned bl = 0xffffffffu;
                float bwx = 0.f; int bslot = so;
                #pragma unroll
                for (int k = 0; k < PPT; ++k){
                    if (mind[k] == bestv){
                        unsigned li = s_lidx[so+k];
                        if (li < bl){ bl = li; bwx = wxr[k]; bslot = so+k; }
                    }
                }
                gmax = bestv;
                pwx = bwx; pslot = bslot;
                gkey = ((unsigned long long)fenc(bestv) << 32)
                     | (unsigned)(~((unsigned)base + bl));
            }
        }

        // block reduce over 384 thread keys
        unsigned long long k1 = warp_max_u64(gkey);
        if (lane == 0) s_red[wid] = k1;
        __syncthreads();
        unsigned long long bk = s_red[0];
        #pragma unroll
        for (int w = 1; w < NW; ++w) if (s_red[w] > bk) bk = s_red[w];

        // winner thread posts key + coords (wy/wz: dynamic SMEM read is fine)
        if (gkey == bk){
            uint4 hb = make_uint4(tag, __float_as_uint(s_wy[pslot]),
                                       __float_as_uint(s_wz[pslot]), 0u);
            uint4 ha = make_uint4(tag, (unsigned)(bk >> 32), (unsigned)bk,
                                       __float_as_uint(pwx));
            st_rlx_v4(&g_partB[p][cta], hb);
            st_rel_v4(&g_partA[p][cta], ha);  // release orders partB before partA
        }

        // gather all CTA partials (tag-gated, parity double-buffered)
        unsigned long long gk = 0ull; float gwx = 0.f, gwy = 0.f, gwz = 0.f;
        if (t < GRID_F){
            uint4 a;
            do { a = ld_acq_v4(&g_partA[p][t]); } while (a.x < tag);
            uint4 b = ld_rlx_v4(&g_partB[p][t]);
            gk  = ((unsigned long long)a.y << 32) | a.z;
            gwx = __uint_as_float(a.w);
            gwy = __uint_as_float(b.y);
            gwz = __uint_as_float(b.z);
        }
        unsigned long long k2 = warp_max_u64(gk);
        if (lane == 0) s_red2[wid] = k2;
        __syncthreads();
        unsigned long long bk2 = s_red2[0];
        #pragma unroll
        for (int w = 1; w < NW; ++w) if (s_red2[w] > bk2) bk2 = s_red2[w];

        if (t < GRID_F && gk == bk2){           // keys unique -> exactly one thread
            s_bc[0] = gwx; s_bc[1] = gwy; s_bc[2] = gwz;
            if (cta == 0) g_sel[it+1] = (int)(~(unsigned)(bk2 & 0xffffffffull));
        }
        __syncthreads();
    }
}

// ---------------- gather selected features ----------------
__global__ void gather_kernel(const float* __restrict__ x, float* __restrict__ feat){
    int t = threadIdx.x;                 // 512 threads
    int idx = g_sel[t];
    float wx, wy, wz; bool v;
    worldpt(x, idx, wx, wy, wz, v);
    feat[t*6+0] = wx;
    feat[t*6+1] = wy;
    feat[t*6+2] = wz;
    feat[t*6+3] = __fdiv_rn(x[idx*5+0], 255.0f);
    feat[t*6+4] = __fdiv_rn(x[idx*5+1], 255.0f);
    feat[t*6+5] = __fdiv_rn(x[idx*5+2], 255.0f);
}

// ---------------- MLP ----------------
template<int D>
__device__ __forceinline__ float block_sum(float v, float* s_red){
    __syncthreads();
    int lane = threadIdx.x & 31, w = threadIdx.x >> 5;
    #pragma unroll
    for (int o = 16; o; o >>= 1) v += __shfl_xor_sync(0xffffffffu, v, o);
    if (lane == 0) s_red[w] = v;
    __syncthreads();
    float s = (threadIdx.x < (D+31)/32) ? s_red[threadIdx.x] : 0.f;
    #pragma unroll
    for (int o = 16; o; o >>= 1) s += __shfl_xor_sync(0xffffffffu, s, o);
    if (threadIdx.x == 0) s_red[0] = s;
    __syncthreads();
    return s_red[0];
}

template<int DIN, int DOUT, bool LNRELU>
__global__ void __launch_bounds__(DOUT) layer_kernel(
    const float* __restrict__ in, const float* __restrict__ W,
    const float* __restrict__ b,  const float* __restrict__ g,
    const float* __restrict__ be, float* __restrict__ out)
{
    __shared__ float s_in[DIN];
    __shared__ float s_red[32];
    const int p = blockIdx.x, t = threadIdx.x;
    for (int k = t; k < DIN; k += DOUT) s_in[k] = in[p*DIN + k];
    __syncthreads();
    float a = b[t];
    #pragma unroll 8
    for (int k = 0; k < DIN; ++k) a = fmaf(s_in[k], W[k*DOUT + t], a);
    if (LNRELU){
        float mean = block_sum<DOUT>(a, s_red) / (float)DOUT;
        float q = a - mean;
        float var = block_sum<DOUT>(q*q, s_red) / (float)DOUT;
        float v = q * rsqrtf(var + 1e-5f) * g[t] + be[t];
        out[p*DOUT + t] = fmaxf(v, 0.f);
    } else {
        out[p*DOUT + t] = a;
    }
}

__global__ void __launch_bounds__(512) final_kernel(
    const float* __restrict__ h4, const float* __restrict__ Wf,
    const float* __restrict__ bf, const float* __restrict__ gf,
    const float* __restrict__ bef, float* __restrict__ out)
{
    __shared__ float pooled[512];
    __shared__ float o[64];
    __shared__ float s_red[4];
    const int t = threadIdx.x;
    float m = ninff();
    for (int p = 0; p < KSEL; ++p) m = fmaxf(m, h4[p*512 + t]);
    pooled[t] = m;
    __syncthreads();
    if (t < 64){
        float a = bf[t];
        #pragma unroll 8
        for (int d = 0; d < 512; ++d) a = fmaf(pooled[d], Wf[d*64 + t], a);
        o[t] = a;
    }
    __syncthreads();
    if (t < 64){
        float s = o[t];
        #pragma unroll
        for (int off = 16; off; off >>= 1) s += __shfl_xor_sync(0xffffffffu, s, off);
        if ((t & 31) == 0) s_red[t >> 5] = s;
    }
    __syncthreads();
    float mean = (s_red[0] + s_red[1]) / 64.f;
    if (t < 64){
        float q = o[t] - mean;
        float s2 = q*q;
        #pragma unroll
        for (int off = 16; off; off >>= 1) s2 += __shfl_xor_sync(0xffffffffu, s2, off);
        if ((t & 31) == 0) s_red[2 + (t >> 5)] = s2;
    }
    __syncthreads();
    if (t < 64){
        float var = (s_red[2] + s_red[3]) / 64.f;
        out[t] = (o[t] - mean) * rsqrtf(var + 1e-5f) * gf[t] + bef[t];
    }
}

// ---------------- launch ----------------
extern "C" void kernel_launch(void* const* d_in, const int* in_sizes, int n_in,
                              void* d_out, int out_size) {
    const float* x = (const float*)d_in[0];
    const float *W1,*b1,*g1,*be1,*W2,*b2,*g2,*be2,*W3,*b3,*g3,*be3,*W4,*b4,*Wf,*bf,*gf,*bef;
    if (n_in > 3 && in_sizes[3] == 64) {
        W1=(const float*)d_in[1];  b1=(const float*)d_in[2];  g1=(const float*)d_in[3];  be1=(const float*)d_in[4];
        W2=(const float*)d_in[5];  b2=(const float*)d_in[6];  g2=(const float*)d_in[7];  be2=(const float*)d_in[8];
        W3=(const float*)d_in[9];  b3=(const float*)d_in[10]; g3=(const float*)d_in[11]; be3=(const float*)d_in[12];
        W4=(const float*)d_in[13]; b4=(const float*)d_in[14];
        Wf=(const float*)d_in[15]; bf=(const float*)d_in[16]; gf=(const float*)d_in[17]; bef=(const float*)d_in[18];
    } else {
        W1=(const float*)d_in[1];  b1=(const float*)d_in[2];
        W2=(const float*)d_in[3];  b2=(const float*)d_in[4];
        W3=(const float*)d_in[5];  b3=(const float*)d_in[6];
        W4=(const float*)d_in[7];  b4=(const float*)d_in[8];
        g1=(const float*)d_in[9];  be1=(const float*)d_in[10];
        g2=(const float*)d_in[11]; be2=(const float*)d_in[12];
        g3=(const float*)d_in[13]; be3=(const float*)d_in[14];
        Wf=(const float*)d_in[15]; bf=(const float*)d_in[16]; gf=(const float*)d_in[17]; bef=(const float*)d_in[18];
    }

    (void)cudaFuncSetAttribute(fps_kernel, cudaFuncAttributeMaxDynamicSharedMemorySize, SMEM_BYTES);

    float *feat,*h1,*h2,*h3,*h4;
    cudaGetSymbolAddress((void**)&feat, g_feat);
    cudaGetSymbolAddress((void**)&h1,   g_h1);
    cudaGetSymbolAddress((void**)&h2,   g_h2);
    cudaGetSymbolAddress((void**)&h3,   g_h3);
    cudaGetSymbolAddress((void**)&h4,   g_h4);

    noop_kernel<<<1, 1>>>();
    noop_kernel<<<1, 1>>>();
    noop_kernel<<<1, 1>>>();
    fps_kernel<<<GRID_F, TPB, SMEM_BYTES>>>(x);     // 4th launch (ncu capture slot)
    gather_kernel<<<1, 512>>>(x, feat);
    layer_kernel<  6,  64, true ><<<KSEL,  64>>>(feat, W1, b1, g1, be1, h1);
    layer_kernel< 64, 128, true ><<<KSEL, 128>>>(h1,   W2, b2, g2, be2, h2);
    layer_kernel<128, 256, true ><<<KSEL, 256>>>(h2,   W3, b3, g3, be3, h3);
    layer_kernel<256, 512, false><<<KSEL, 512>>>(h3,   W4, b4, nullptr, nullptr, h4);
    final_kernel<<<1, 512>>>(h4, Wf, bf, gf, bef, (float*)d_out);
}

// round 14
// speedup vs baseline: 1.8089x; 1.1646x over previous
#include <cuda_runtime.h>
#include <cstdint>

// ---------------- problem constants ----------------
#define NPTS    (64*224*224)      // 3,211,264 points
#define KSEL    512
#define TPB     384
#define PPT     57
#define CTA_PTS (TPB*PPT)         // 21888
#define GRID_F  147               // 147*21888 = 3,217,536 >= NPTS
#define NW      12                // warps per CTA
#define NZB     32
#define NTILE   28                // 4 row-blocks (64 rows) x 7 col-blocks (32 cols)
#define NGV     (NZB*NTILE)       // 896 valid groups (serpentine ordered)
#define NG_TOT  (NGV+1)           // + junk group

#define FXF  ((float)(11200.0/20.995))        // WIDTH*FOCAL/20.995
#define COSF ((float)0.8386705679454240)      // cos(33 deg)
#define SINF ((float)0.5446390350150271)      // sin(33 deg)

// ---- dynamic smem layout (bytes) ----
#define OFF_WY     0                          // f32[21888] stride-57 per thread (gcd(57,32)=1)
#define OFF_WZ     87552
#define OFF_LIDX   175104                     // u16[21888]
#define OFF_UG     218880                     // f32[224] (ug == vg table)
#define OFF_START  219776                     // u32[NG_TOT+1]
#define OFF_CUR    223368                     // u32[NG_TOT]
#define SMEM_BYTES 226956

__device__ __forceinline__ float pinff(){ return __int_as_float(0x7f800000); }
__device__ __forceinline__ float ninff(){ return __int_as_float(0xff800000); }

__device__ __forceinline__ unsigned fenc(float f){
    unsigned u = __float_as_uint(f);
    return (u & 0x80000000u) ? ~u : (u | 0x80000000u);
}
__device__ __forceinline__ unsigned ld_acq_u32(const unsigned* p){
    unsigned v;
    asm volatile("ld.acquire.gpu.global.b32 %0, [%1];" : "=r"(v) : "l"(p) : "memory");
    return v;
}
__device__ __forceinline__ uint4 ld_acq_v4(const uint4* p){
    uint4 v;
    asm volatile("ld.acquire.gpu.global.v4.b32 {%0,%1,%2,%3}, [%4];"
                 : "=r"(v.x), "=r"(v.y), "=r"(v.z), "=r"(v.w) : "l"(p) : "memory");
    return v;
}
__device__ __forceinline__ uint4 ld_rlx_v4(const uint4* p){
    uint4 v;
    asm volatile("ld.relaxed.gpu.global.v4.b32 {%0,%1,%2,%3}, [%4];"
                 : "=r"(v.x), "=r"(v.y), "=r"(v.z), "=r"(v.w) : "l"(p) : "memory");
    return v;
}
__device__ __forceinline__ void st_rlx_v4(uint4* p, uint4 v){
    asm volatile("st.relaxed.gpu.global.v4.b32 [%0], {%1,%2,%3,%4};"
                 :: "l"(p), "r"(v.x), "r"(v.y), "r"(v.z), "r"(v.w) : "memory");
}
__device__ __forceinline__ void st_rel_v4(uint4* p, uint4 v){
    asm volatile("st.release.gpu.global.v4.b32 [%0], {%1,%2,%3,%4};"
                 :: "l"(p), "r"(v.x), "r"(v.y), "r"(v.z), "r"(v.w) : "memory");
}
__device__ __forceinline__ unsigned long long warp_max_u64(unsigned long long v){
    #pragma unroll
    for (int o = 16; o; o >>= 1){
        unsigned long long w = __shfl_down_sync(0xffffffffu, v, o);
        if (w > v) v = w;
    }
    return v;
}

// serpentine 3D group id: every gid->gid+1 step is spatially adjacent (no Z wrap)
__device__ __forceinline__ int serp_gid(int row, int col, float Z){
    int zb = min(NZB-1, (int)(Z * (float)NZB));
    int rb = row >> 6;                         // 0..3 (64-row blocks)
    int cb = col >> 5;                         // 0..6 (32-col blocks)
    int tl = (rb & 1) ? (rb*7 + (6 - cb)) : (rb*7 + cb);
    return zb * NTILE + ((zb & 1) ? (NTILE-1 - tl) : tl);
}

// ---------------- device scratch (zero-initialized at load) ----------------
__device__ uint4         g_partA[2][GRID_F];   // {tag, keyhi, keylo, wx}
__device__ uint4         g_partB[2][GRID_F];   // {tag, wy, wz, 0}
__device__ int           g_first[GRID_F];
__device__ unsigned int  g_ready;              // monotonic ticket counter
__device__ int           g_sel[KSEL];
__device__ float         g_feat[KSEL*6];
__device__ float         g_h1[KSEL*64];
__device__ float         g_h2[KSEL*128];
__device__ float         g_h3[KSEL*256];
__device__ float         g_h4[KSEL*512];

// world-space point, reference fp32 association (no fma contraction)
__device__ __forceinline__ void worldpt(const float* __restrict__ x, int idx,
                                        float& wx, float& wy, float& wz, bool& valid){
    float Z   = __ldg(&x[idx*5+3]);
    float seg = __ldg(&x[idx*5+4]);
    int col =  idx % 224;
    int row = (idx / 224) % 224;
    float ug = __fdiv_rn((float)(112 - col), FXF);
    float vg = __fdiv_rn((float)(112 - row), FXF);
    float X = __fmul_rn(ug, Z);
    float Y = __fmul_rn(vg, Z);
    wx = X;
    wy = __fadd_rn(__fsub_rn(__fmul_rn(Y, COSF), __fmul_rn(Z, SINF)),  1.5f);
    wz = __fadd_rn(__fadd_rn(__fmul_rn(Y, SINF), __fmul_rn(Z, COSF)), -2.5f);
    valid = (Z < 3.0f) && (seg != 15.0f);
}

__global__ void noop_kernel(){}

// ---------------- persistent FPS kernel ----------------
__global__ void __launch_bounds__(TPB,1) fps_kernel(const float* __restrict__ x){
    extern __shared__ unsigned char smraw[];
    float*    s_wy    = (float*)(smraw + OFF_WY);
    float*    s_wz    = (float*)(smraw + OFF_WZ);
    unsigned short* s_lidx = (unsigned short*)(smraw + OFF_LIDX);
    float*    s_ug    = (float*)(smraw + OFF_UG);   // ug == vg (same table)
    unsigned* s_start = (unsigned*)(smraw + OFF_START);
    unsigned* s_cur   = (unsigned*)(smraw + OFF_CUR);

    __shared__ float s_bc[3];
    __shared__ int   s_fv;
    __shared__ unsigned s_epoch;
    __shared__ unsigned long long s_red[NW];
    __shared__ unsigned long long s_red2[NW];

    const int t    = threadIdx.x;
    const int cta  = blockIdx.x;
    const int base = cta * CTA_PTS;
    const int wid  = t >> 5, lane = t & 31;
    const int so   = t * PPT;          // owned slot range [so, so+57)

    if (t == 0) s_fv = 0x7fffffff;
    for (int i = t; i < 224; i += TPB)
        s_ug[i] = __fdiv_rn((float)(112 - i), FXF);
    for (int g = t; g < NG_TOT; g += TPB) s_cur[g] = 0u;
    __syncthreads();

    // ---- pass 1: histogram ----
    int firstvalid = 0x7fffffff;
    for (int k = 0; k < PPT; ++k){
        int lidx = k*TPB + t;
        int fl   = base + lidx;
        int gid  = NGV;
        if (fl < NPTS){
            float Z   = __ldg(&x[fl*5+3]);
            float seg = __ldg(&x[fl*5+4]);
            bool valid = (Z < 3.0f) && (seg != 15.0f);
            if (valid){
                if (fl < firstvalid) firstvalid = fl;
                int col = fl % 224;
                int row = (fl / 224) % 224;
                gid = serp_gid(row, col, Z);
            }
        }
        atomicAdd(&s_cur[gid], 1u);
    }
    atomicMin(&s_fv, firstvalid);
    __syncthreads();

    // ---- pass 2: serial prefix ----
    if (t == 0){
        unsigned acc = 0;
        for (int g = 0; g < NG_TOT; ++g){
            unsigned c = s_cur[g];
            s_start[g] = acc; s_cur[g] = acc; acc += c;
        }
        s_start[NG_TOT] = acc;
    }
    __syncthreads();

    // ---- pass 3: scatter (exact wy/wz) ----
    for (int k = 0; k < PPT; ++k){
        int lidx = k*TPB + t;
        int fl   = base + lidx;
        int gid  = NGV;
        float wy = 0.f, wz = 0.f;
        if (fl < NPTS){
            float Z   = __ldg(&x[fl*5+3]);
            float seg = __ldg(&x[fl*5+4]);
            bool valid = (Z < 3.0f) && (seg != 15.0f);
            if (valid){
                int col = fl % 224;
                int row = (fl / 224) % 224;
                gid = serp_gid(row, col, Z);
                float Y = __fmul_rn(s_ug[row], Z);
                wy = __fadd_rn(__fsub_rn(__fmul_rn(Y, COSF), __fmul_rn(Z, SINF)),  1.5f);
                wz = __fadd_rn(__fadd_rn(__fmul_rn(Y, SINF), __fmul_rn(Z, COSF)), -2.5f);
            }
        }
        unsigned pos = atomicAdd(&s_cur[gid], 1u);
        s_wy[pos] = wy;
        s_wz[pos] = wz;
        s_lidx[pos] = (unsigned short)lidx;
    }
    __syncthreads();

    // ---- owner init: thread owns sorted slots [so, so+57) ----
    float mind[PPT];
    float wxr [PPT];
    float ax = 0.f, ay = 0.f, az = 0.f, rad = 0.f;
    float gmax;
    unsigned long long gkey;
    float pwx = 0.f; int pslot = 0;           // winner coord cache (wx + slot)
    {
        const unsigned junkstart = s_start[NGV];
        bool anyv = false; float maxd2 = 0.f;
        #pragma unroll 4
        for (int k = 0; k < PPT; ++k){
            unsigned pos = (unsigned)(so + k);
            bool valid = pos < junkstart;
            float wx = 0.f;
            if (valid){
                int fl = base + (int)s_lidx[pos];
                float Z = __ldg(&x[fl*5+3]);
                wx = __fmul_rn(s_ug[fl % 224], Z);
            }
            wxr[k]  = wx;
            mind[k] = valid ? pinff() : ninff();
            if (valid){
                float wy = s_wy[pos], wz = s_wz[pos];
                if (!anyv){ ax = wx; ay = wy; az = wz; anyv = true; }
                float dx = wx-ax, dy = wy-ay, dz = wz-az;
                maxd2 = fmaxf(maxd2, dx*dx + dy*dy + dz*dz);
            }
        }
        rad  = sqrtf(maxd2) * (1.0f + 1e-5f) + 1e-7f;
        gmax = anyv ? pinff() : ninff();
        gkey = ((unsigned long long)fenc(gmax) << 32);
    }
    __syncthreads();

    // ---- epoch-ticketed grid barrier (replay-idempotent) ----
    if (t == 0){
        g_first[cta] = s_fv;
        __threadfence();
        unsigned ticket = atomicAdd(&g_ready, 1u);
        unsigned epoch  = ticket / GRID_F;
        unsigned target = (epoch + 1u) * GRID_F;
        while (ld_acq_u32(&g_ready) < target) { }
        s_epoch = epoch;
    }
    __syncthreads();
    const unsigned tagbase = s_epoch * (unsigned)KSEL + 1u;

    // ---- deterministic start ----
    {
        unsigned fv = 0x7fffffffu;
        if (t < GRID_F) fv = ld_acq_u32((const unsigned*)&g_first[t]);
        fv = __reduce_min_sync(0xffffffffu, fv);
        if (lane == 0) s_red[wid] = fv;
        __syncthreads();
        if (t == 0){
            unsigned s = (unsigned)s_red[0];
            for (int w = 1; w < NW; ++w) s = min(s, (unsigned)s_red[w]);
            int sp = (s == 0x7fffffffu) ? 0 : (int)s;
            float wx, wy, wz; bool v;
            worldpt(x, sp, wx, wy, wz, v);
            s_bc[0] = wx; s_bc[1] = wy; s_bc[2] = wz;
            if (cta == 0) g_sel[0] = sp;
        }
        __syncthreads();
    }

    // ---- 511 rounds ----
    for (int it = 0; it < KSEL-1; ++it){
        const float cx = s_bc[0], cy = s_bc[1], cz = s_bc[2];
        const unsigned tag = tagbase + (unsigned)it;
        const int p = it & 1;

        // exact chunk prune test (conservative margins; skipped updates provably no-ops)
        {
            float dx = cx-ax, dy = cy-ay, dz = cz-az;
            float dc = sqrtf(dx*dx + dy*dy + dz*dz);
            float lb = dc * (1.0f - 1e-5f) - rad;
            bool prune = (lb > 0.f) && (lb*lb*(1.0f - 1e-5f) > gmax*(1.0f + 1e-5f));
            if (!prune){
                // pass 1: distance update + running max (short FMNMX chain)
                float bestv = ninff();
                #pragma unroll
                for (int k = 0; k < PPT; ++k){
                    float dxx = __fsub_rn(wxr[k],     cx);
                    float dyy = __fsub_rn(s_wy[so+k], cy);
                    float dzz = __fsub_rn(s_wz[so+k], cz);
                    float d   = __fadd_rn(__fadd_rn(__fmul_rn(dxx,dxx), __fmul_rn(dyy,dyy)),
                                          __fmul_rn(dzz,dzz));
                    float m = fminf(mind[k], d);
                    mind[k] = m;
                    bestv   = fmaxf(bestv, m);
                }
                // pass 2: argmax (lowest lidx) + static capture of wx and slot
                unsigned bl = 0xffffffffu;
                float bwx = 0.f; int bslot = so;
                #pragma unroll
                for (int k = 0; k < PPT; ++k){
                    if (mind[k] == bestv){
                        unsigned li = s_lidx[so+k];
                        if (li < bl){ bl = li; bwx = wxr[k]; bslot = so+k; }
                    }
                }
                gmax = bestv;
                pwx = bwx; pslot = bslot;
                gkey = ((unsigned long long)fenc(bestv) << 32)
                     | (unsigned)(~((unsigned)base + bl));
            }
        }

        // block reduce over 384 thread keys
        unsigned long long k1 = warp_max_u64(gkey);
        if (lane == 0) s_red[wid] = k1;
        __syncthreads();
        unsigned long long bk = s_red[0];
        #pragma unroll
        for (int w = 1; w < NW; ++w) if (s_red[w] > bk) bk = s_red[w];

        // winner thread posts key + coords (wy/wz: dynamic SMEM read is fine)
        if (gkey == bk){
            uint4 hb = make_uint4(tag, __float_as_uint(s_wy[pslot]),
                                       __float_as_uint(s_wz[pslot]), 0u);
            uint4 ha = make_uint4(tag, (unsigned)(bk >> 32), (unsigned)bk,
                                       __float_as_uint(pwx));
            st_rlx_v4(&g_partB[p][cta], hb);
            st_rel_v4(&g_partA[p][cta], ha);  // release orders partB before partA
        }

        // gather all CTA partials (tag-gated, parity double-buffered)
        unsigned long long gk = 0ull; float gwx = 0.f, gwy = 0.f, gwz = 0.f;
        if (t < GRID_F){
            uint4 a;
            do { a = ld_acq_v4(&g_partA[p][t]); } while (a.x < tag);
            uint4 b = ld_rlx_v4(&g_partB[p][t]);
            gk  = ((unsigned long long)a.y << 32) | a.z;
            gwx = __uint_as_float(a.w);
            gwy = __uint_as_float(b.y);
            gwz = __uint_as_float(b.z);
        }
        unsigned long long k2 = warp_max_u64(gk);
        if (lane == 0) s_red2[wid] = k2;
        __syncthreads();
        unsigned long long bk2 = s_red2[0];
        #pragma unroll
        for (int w = 1; w < NW; ++w) if (s_red2[w] > bk2) bk2 = s_red2[w];

        if (t < GRID_F && gk == bk2){           // keys unique -> exactly one thread
            s_bc[0] = gwx; s_bc[1] = gwy; s_bc[2] = gwz;
            if (cta == 0) g_sel[it+1] = (int)(~(unsigned)(bk2 & 0xffffffffull));
        }
        __syncthreads();
    }
}

// ---------------- gather selected features ----------------
__global__ void gather_kernel(const float* __restrict__ x, float* __restrict__ feat){
    int t = threadIdx.x;                 // 512 threads
    int idx = g_sel[t];
    float wx, wy, wz; bool v;
    worldpt(x, idx, wx, wy, wz, v);
    feat[t*6+0] = wx;
    feat[t*6+1] = wy;
    feat[t*6+2] = wz;
    feat[t*6+3] = __fdiv_rn(x[idx*5+0], 255.0f);
    feat[t*6+4] = __fdiv_rn(x[idx*5+1], 255.0f);
    feat[t*6+5] = __fdiv_rn(x[idx*5+2], 255.0f);
}

// ---------------- MLP ----------------
template<int D>
__device__ __forceinline__ float block_sum(float v, float* s_red){
    __syncthreads();
    int lane = threadIdx.x & 31, w = threadIdx.x >> 5;
    #pragma unroll
    for (int o = 16; o; o >>= 1) v += __shfl_xor_sync(0xffffffffu, v, o);
    if (lane == 0) s_red[w] = v;
    __syncthreads();
    float s = (threadIdx.x < (D+31)/32) ? s_red[threadIdx.x] : 0.f;
    #pragma unroll
    for (int o = 16; o; o >>= 1) s += __shfl_xor_sync(0xffffffffu, s, o);
    if (threadIdx.x == 0) s_red[0] = s;
    __syncthreads();
    return s_red[0];
}

template<int DIN, int DOUT, bool LNRELU>
__global__ void __launch_bounds__(DOUT) layer_kernel(
    const float* __restrict__ in, const float* __restrict__ W,
    const float* __restrict__ b,  const float* __restrict__ g,
    const float* __restrict__ be, float* __restrict__ out)
{
    __shared__ float s_in[DIN];
    __shared__ float s_red[32];
    const int p = blockIdx.x, t = threadIdx.x;
    for (int k = t; k < DIN; k += DOUT) s_in[k] = in[p*DIN + k];
    __syncthreads();
    float a = b[t];
    #pragma unroll 8
    for (int k = 0; k < DIN; ++k) a = fmaf(s_in[k], W[k*DOUT + t], a);
    if (LNRELU){
        float mean = block_sum<DOUT>(a, s_red) / (float)DOUT;
        float q = a - mean;
        float var = block_sum<DOUT>(q*q, s_red) / (float)DOUT;
        float v = q * rsqrtf(var + 1e-5f) * g[t] + be[t];
        out[p*DOUT + t] = fmaxf(v, 0.f);
    } else {
        out[p*DOUT + t] = a;
    }
}

__global__ void __launch_bounds__(512) final_kernel(
    const float* __restrict__ h4, const float* __restrict__ Wf,
    const float* __restrict__ bf, const float* __restrict__ gf,
    const float* __restrict__ bef, float* __restrict__ out)
{
    __shared__ float pooled[512];
    __shared__ float o[64];
    __shared__ float s_red[4];
    const int t = threadIdx.x;
    float m = ninff();
    for (int p = 0; p < KSEL; ++p) m = fmaxf(m, h4[p*512 + t]);
    pooled[t] = m;
    __syncthreads();
    if (t < 64){
        float a = bf[t];
        #pragma unroll 8
        for (int d = 0; d < 512; ++d) a = fmaf(pooled[d], Wf[d*64 + t], a);
        o[t] = a;
    }
    __syncthreads();
    if (t < 64){
        float s = o[t];
        #pragma unroll
        for (int off = 16; off; off >>= 1) s += __shfl_xor_sync(0xffffffffu, s, off);
        if ((t & 31) == 0) s_red[t >> 5] = s;
    }
    __syncthreads();
    float mean = (s_red[0] + s_red[1]) / 64.f;
    if (t < 64){
        float q = o[t] - mean;
        float s2 = q*q;
        #pragma unroll
        for (int off = 16; off; off >>= 1) s2 += __shfl_xor_sync(0xffffffffu, s2, off);
        if ((t & 31) == 0) s_red[2 + (t >> 5)] = s2;
    }
    __syncthreads();
    if (t < 64){
        float var = (s_red[2] + s_red[3]) / 64.f;
        out[t] = (o[t] - mean) * rsqrtf(var + 1e-5f) * gf[t] + bef[t];
    }
}

// ---------------- launch ----------------
extern "C" void kernel_launch(void* const* d_in, const int* in_sizes, int n_in,
                              void* d_out, int out_size) {
    const float* x = (const float*)d_in[0];
    const float *W1,*b1,*g1,*be1,*W2,*b2,*g2,*be2,*W3,*b3,*g3,*be3,*W4,*b4,*Wf,*bf,*gf,*bef;
    if (n_in > 3 && in_sizes[3] == 64) {
        W1=(const float*)d_in[1];  b1=(const float*)d_in[2];  g1=(const float*)d_in[3];  be1=(const float*)d_in[4];
        W2=(const float*)d_in[5];  b2=(const float*)d_in[6];  g2=(const float*)d_in[7];  be2=(const float*)d_in[8];
        W3=(const float*)d_in[9];  b3=(const float*)d_in[10]; g3=(const float*)d_in[11]; be3=(const float*)d_in[12];
        W4=(const float*)d_in[13]; b4=(const float*)d_in[14];
        Wf=(const float*)d_in[15]; bf=(const float*)d_in[16]; gf=(const float*)d_in[17]; bef=(const float*)d_in[18];
    } else {
        W1=(const float*)d_in[1];  b1=(const float*)d_in[2];
        W2=(const float*)d_in[3];  b2=(const float*)d_in[4];
        W3=(const float*)d_in[5];  b3=(const float*)d_in[6];
        W4=(const float*)d_in[7];  b4=(const float*)d_in[8];
        g1=(const float*)d_in[9];  be1=(const float*)d_in[10];
        g2=(const float*)d_in[11]; be2=(const float*)d_in[12];
        g3=(const float*)d_in[13]; be3=(const float*)d_in[14];
        Wf=(const float*)d_in[15]; bf=(const float*)d_in[16]; gf=(const float*)d_in[17]; bef=(const float*)d_in[18];
    }

    (void)cudaFuncSetAttribute(fps_kernel, cudaFuncAttributeMaxDynamicSharedMemorySize, SMEM_BYTES);

    float *feat,*h1,*h2,*h3,*h4;
    cudaGetSymbolAddress((void**)&feat, g_feat);
    cudaGetSymbolAddress((void**)&h1,   g_h1);
    cudaGetSymbolAddress((void**)&h2,   g_h2);
    cudaGetSymbolAddress((void**)&h3,   g_h3);
    cudaGetSymbolAddress((void**)&h4,   g_h4);

    noop_kernel<<<1, 1>>>();
    noop_kernel<<<1, 1>>>();
    noop_kernel<<<1, 1>>>();
    fps_kernel<<<GRID_F, TPB, SMEM_BYTES>>>(x);     // 4th launch (ncu capture slot)
    gather_kernel<<<1, 512>>>(x, feat);
    layer_kernel<  6,  64, true ><<<KSEL,  64>>>(feat, W1, b1, g1, be1, h1);
    layer_kernel< 64, 128, true ><<<KSEL, 128>>>(h1,   W2, b2, g2, be2, h2);
    layer_kernel<128, 256, true ><<<KSEL, 256>>>(h2,   W3, b3, g3, be3, h3);
    layer_kernel<256, 512, false><<<KSEL, 512>>>(h3,   W4, b4, nullptr, nullptr, h4);
    final_kernel<<<1, 512>>>(h4, Wf, bf, gf, bef, (float*)d_out);
}